// round 6
// baseline (speedup 1.0000x reference)
#include <cuda_runtime.h>
#include <cuda.h>
#include <cstdint>
#include <dlfcn.h>

#if defined(__CUDA_ARCH__) && (defined(__CUDA_ARCH_FEAT_SM103_ALL) || defined(__CUDA_ARCH_SPECIFIC__) || defined(__CUDA_ARCH_FAMILY_SPECIFIC__))
#define HAS_TCG 1
#else
#define HAS_TCG 0
#endif

#define N_ROWS 16384
#define D_IN   512
#define D_OUT  128

#define KT 32                       // K per stage (32 fp32 = 128B rows, SW128)
#define MT 128
#define STAGES 6
#define A_BYTES 16384               // 128 rows x 128B
#define B_BYTES 16384
#define STAGE_BYTES (A_BYTES + B_BYTES)
#define SMEM_DYN (2048 + STAGES * STAGE_BYTES)
#define NTHREADS 320                // warps 0-7 compute (fallback), 8 producer, 9 tcg issuer

// idesc kind::tf32: dtype F32=1<<4, atype TF32=2<<7, btype TF32=2<<10, N/8<<17, M/16<<24
#define IDESC_TF32 ((1u << 4) | (2u << 7) | (2u << 10) | (16u << 17) | (8u << 24))

// Static scratch (allocation-free)
__device__ __align__(1024) float g_Wt[D_OUT * D_IN];
__device__ __align__(1024) float g_Xt[(size_t)D_OUT * N_ROWS];
__device__ __align__(1024) float g_inR[(size_t)N_ROWS * D_IN];

// ---------------- helpers (non-arch-specific) ----------------
__device__ __forceinline__ uint32_t smem_u32(const void* p) {
    uint32_t a;
    asm("{ .reg .u64 t; cvta.to.shared.u64 t, %1; cvt.u32.u64 %0, t; }" : "=r"(a) : "l"(p));
    return a;
}
__device__ __forceinline__ uint32_t cluster_rank() {
    uint32_t r; asm("mov.u32 %0, %%cluster_ctarank;" : "=r"(r));
    return r;
}
__device__ __forceinline__ void cluster_sync_all() {
    asm volatile("barrier.cluster.arrive.aligned;" ::: "memory");
    asm volatile("barrier.cluster.wait.aligned;" ::: "memory");
}
__device__ __forceinline__ float rna_tf32(float x) {
    float r; asm("cvt.rna.tf32.f32 %0, %1;" : "=f"(r) : "f"(x));
    return r;
}
__device__ __forceinline__ void mbar_init(uint32_t a, uint32_t cnt) {
    asm volatile("mbarrier.init.shared.b64 [%0], %1;" :: "r"(a), "r"(cnt) : "memory");
}
__device__ __forceinline__ void mbar_arrive(uint32_t a) {
    asm volatile("mbarrier.arrive.shared.b64 _, [%0];" :: "r"(a) : "memory");
}
__device__ __forceinline__ void mbar_expect_tx(uint32_t a, uint32_t bytes) {
    asm volatile("mbarrier.arrive.expect_tx.shared.b64 _, [%0], %1;" :: "r"(a), "r"(bytes) : "memory");
}
__device__ __forceinline__ void mbar_wait_acq(uint32_t a, uint32_t ph) {
    asm volatile("{\n\t.reg .pred P1;\n\t"
                 "WA_%=:\n\t"
                 "mbarrier.try_wait.parity.acquire.cta.shared::cta.b64 P1, [%0], %1, 0x989680;\n\t"
                 "@P1 bra.uni WDA_%=;\n\t"
                 "bra.uni WA_%=;\n\t"
                 "WDA_%=:\n\t}" :: "r"(a), "r"(ph) : "memory");
}
__device__ __forceinline__ void mbar_wait_rel(uint32_t a, uint32_t ph) {
    asm volatile("{\n\t.reg .pred P1;\n\t"
                 "WR_%=:\n\t"
                 "mbarrier.try_wait.parity.relaxed.cta.shared::cta.b64 P1, [%0], %1, 0x989680;\n\t"
                 "@P1 bra.uni WDR_%=;\n\t"
                 "bra.uni WR_%=;\n\t"
                 "WDR_%=:\n\t}" :: "r"(a), "r"(ph) : "memory");
}
__device__ __forceinline__ void tma_load2d(uint32_t dst, const CUtensorMap* tm,
                                           int cx, int cy, uint32_t bar) {
    asm volatile("cp.async.bulk.tensor.2d.shared::cta.global.tile.mbarrier::complete_tx::bytes "
                 "[%0], [%1, {%2, %3}], [%4];"
                 :: "r"(dst), "l"(tm), "r"(cx), "r"(cy), "r"(bar) : "memory");
}
__device__ __forceinline__ uint32_t sw128(uint32_t o) { return o ^ ((o >> 3) & 0x70); }
__device__ __forceinline__ uint32_t lds32(uint32_t a) {
    uint32_t v; asm volatile("ld.shared.b32 %0, [%1];" : "=r"(v) : "r"(a));
    return v;
}
__device__ __forceinline__ void mma_t4(float* c, const uint32_t* a, uint32_t b0, uint32_t b1) {
    asm volatile("mma.sync.aligned.m16n8k8.row.col.f32.tf32.tf32.f32 "
                 "{%0,%1,%2,%3}, {%4,%5,%6,%7}, {%8,%9}, {%0,%1,%2,%3};"
                 : "+f"(c[0]), "+f"(c[1]), "+f"(c[2]), "+f"(c[3])
                 : "r"(a[0]), "r"(a[1]), "r"(a[2]), "r"(a[3]), "r"(b0), "r"(b1));
}

// ---------------- arch-specific helpers ----------------
#if HAS_TCG
__device__ __forceinline__ void tma_load2d_mc(uint32_t dst, const CUtensorMap* tm,
                                              int cx, int cy, uint32_t bar, uint16_t mask) {
    asm volatile("cp.async.bulk.tensor.2d.shared::cluster.global.tile.mbarrier::complete_tx::bytes.multicast::cluster "
                 "[%0], [%1, {%2, %3}], [%4], %5;"
                 :: "r"(dst), "l"(tm), "r"(cx), "r"(cy), "r"(bar), "h"(mask) : "memory");
}
__device__ __forceinline__ void tc_alloc(uint32_t saddr) {
    asm volatile("tcgen05.alloc.cta_group::1.sync.aligned.shared::cta.b32 [%0], %1;"
                 :: "r"(saddr), "r"(128) : "memory");
}
__device__ __forceinline__ void tc_relinq() {
    asm volatile("tcgen05.relinquish_alloc_permit.cta_group::1.sync.aligned;");
}
__device__ __forceinline__ void tc_dealloc(uint32_t t) {
    asm volatile("tcgen05.dealloc.cta_group::1.sync.aligned.b32 %0, %1;" :: "r"(t), "r"(128));
}
__device__ __forceinline__ void tc_commit(uint32_t bar) {
    asm volatile("tcgen05.commit.cta_group::1.mbarrier::arrive::one.shared::cluster.b64 [%0];"
                 :: "r"(bar) : "memory");
}
__device__ __forceinline__ void tc_commit_mc(uint32_t bar, uint16_t mask) {
    asm volatile("tcgen05.commit.cta_group::1.mbarrier::arrive::one.shared::cluster.multicast::cluster.b64 [%0], %1;"
                 :: "r"(bar), "h"(mask) : "memory");
}
__device__ __forceinline__ void tc_fence_after()  { asm volatile("tcgen05.fence::after_thread_sync;"  ::: "memory"); }
__device__ __forceinline__ void tc_fence_before() { asm volatile("tcgen05.fence::before_thread_sync;" ::: "memory"); }
__device__ __forceinline__ void tc_wait_ld()      { asm volatile("tcgen05.wait::ld.sync.aligned;"     ::: "memory"); }
__device__ __forceinline__ uint64_t sdesc(uint32_t addr) {
    const uint64_t BASE = (2ull << 61) | (1ull << 46) | (64ull << 32) | (1ull << 16);
    return BASE | ((uint64_t)(addr >> 4) & 0x3FFF);
}
__device__ __forceinline__ void mma_tf32(uint32_t d, uint64_t ad, uint64_t bd, uint32_t en) {
    asm volatile("{\n\t.reg .pred p;\n\tsetp.ne.u32 p, %4, 0;\n\t"
                 "tcgen05.mma.cta_group::1.kind::tf32 [%0], %1, %2, %3, {%5, %5, %5, %5}, p;\n\t}"
                 :: "r"(d), "l"(ad), "l"(bd), "r"(IDESC_TF32), "r"(en), "r"(0u) : "memory");
}
__device__ __forceinline__ void tc_ld_x32(uint32_t* r, uint32_t ta) {
    asm volatile("tcgen05.ld.sync.aligned.32x32b.x32.b32 "
        "{%0, %1, %2, %3, %4, %5, %6, %7, "
        " %8, %9, %10, %11, %12, %13, %14, %15, "
        " %16, %17, %18, %19, %20, %21, %22, %23, "
        " %24, %25, %26, %27, %28, %29, %30, %31}, [%32];"
        : "=r"(r[0]),  "=r"(r[1]),  "=r"(r[2]),  "=r"(r[3]),
          "=r"(r[4]),  "=r"(r[5]),  "=r"(r[6]),  "=r"(r[7]),
          "=r"(r[8]),  "=r"(r[9]),  "=r"(r[10]), "=r"(r[11]),
          "=r"(r[12]), "=r"(r[13]), "=r"(r[14]), "=r"(r[15]),
          "=r"(r[16]), "=r"(r[17]), "=r"(r[18]), "=r"(r[19]),
          "=r"(r[20]), "=r"(r[21]), "=r"(r[22]), "=r"(r[23]),
          "=r"(r[24]), "=r"(r[25]), "=r"(r[26]), "=r"(r[27]),
          "=r"(r[28]), "=r"(r[29]), "=r"(r[30]), "=r"(r[31])
        : "r"(ta));
}
#endif

// ---------------- GEMM body: C[M,128] = A[M,K] * Bt[128,K]^T ----------------
// CSZ>1: B tile cooperatively sliced + multicast across the cluster.
template<int CSZ>
__device__ __forceinline__ void gemm_body(const CUtensorMap& tmA, const CUtensorMap& tmB,
                                          float* __restrict__ C, int kIters, int storeT)
{
    extern __shared__ __align__(1024) char smem_raw[];
    uint32_t sb = smem_u32(smem_raw);
    uint32_t ab = (sb + 1023u) & ~1023u;
    const uint32_t DONE  = ab + STAGES * 16;
    const uint32_t TPTR  = ab + 128;
    const uint32_t TILE0 = ab + 1024;
    int tid = threadIdx.x, wid = tid >> 5, lane = tid & 31;
    uint32_t rank = (CSZ > 1) ? cluster_rank() : 0;

#if HAS_TCG
    const uint32_t EMPTY_CNT = CSZ;   // one commit(-multicast) per cluster CTA
#else
    const uint32_t EMPTY_CNT = 8;     // 8 local consumer warps
#endif
    if (tid == 0) {
        for (int s = 0; s < STAGES; s++) {
            mbar_init(ab + s*16, 1);               // full (tx-based)
            mbar_init(ab + s*16 + 8, EMPTY_CNT);   // empty
        }
        mbar_init(DONE, 1);
    }
#if HAS_TCG
    if (wid == 0) { tc_alloc(TPTR); tc_relinq(); }
#endif
    __syncthreads();
    if (CSZ > 1) cluster_sync_all();   // mbarriers visible before any multicast TMA

#if HAS_TCG
    uint32_t tmem;
    asm volatile("ld.shared.b32 %0, [%1];" : "=r"(tmem) : "r"(TPTR));
#endif

    if (tid == 256) {                 // ---- producer (warp 8 lane 0) ----
        int s = 0, ph = 1;
        int mo = blockIdx.x * MT;
        for (int it = 0; it < kIters; ++it) {
            mbar_wait_rel(ab + s*16 + 8, ph);
            mbar_expect_tx(ab + s*16, STAGE_BYTES);
            uint32_t base = TILE0 + s * STAGE_BYTES;
            tma_load2d(base, &tmA, it * KT, mo, ab + s*16);
            if (CSZ == 1) {
                tma_load2d(base + A_BYTES, &tmB, it * KT, 0, ab + s*16);
            } else {
#if HAS_TCG
                // each CTA loads its 128/CSZ-row slice, multicast to whole cluster
                tma_load2d_mc(base + A_BYTES + rank * (B_BYTES / CSZ), &tmB,
                              it * KT, (int)(rank * (128 / CSZ)), ab + s*16,
                              (uint16_t)((1u << CSZ) - 1u));
#else
                #pragma unroll
                for (int r = 0; r < CSZ; ++r)
                    tma_load2d(base + A_BYTES + r * (B_BYTES / CSZ), &tmB,
                               it * KT, r * (128 / CSZ), ab + s*16);
#endif
            }
            if (++s == STAGES) { s = 0; ph ^= 1; }
        }
    }
#if HAS_TCG
    else if (tid == 288) {            // ---- tcgen05 MMA issuer (warp 9 lane 0) ----
        int s = 0, ph = 0;
        for (int it = 0; it < kIters; ++it) {
            mbar_wait_rel(ab + s*16, ph);
            uint32_t base = TILE0 + s * STAGE_BYTES;
            uint64_t ad = sdesc(base), bd = sdesc(base + A_BYTES);
            mma_tf32(tmem, ad,     bd,     it != 0);
            mma_tf32(tmem, ad + 2, bd + 2, 1);
            mma_tf32(tmem, ad + 4, bd + 4, 1);
            mma_tf32(tmem, ad + 6, bd + 6, 1);
            if (CSZ == 1) tc_commit(ab + s*16 + 8);
            else          tc_commit_mc(ab + s*16 + 8, (uint16_t)((1u << CSZ) - 1u));
            if (++s == STAGES) { s = 0; ph ^= 1; }
        }
        tc_commit(DONE);
    }
    // ---- epilogue: everyone waits, warps 0-3 drain TMEM ----
    mbar_wait_acq(DONE, 0);
    tc_fence_after();
    if (wid < 4) {
        uint32_t r[32];
        int m = blockIdx.x * MT + wid * 32 + lane;
        #pragma unroll
        for (int ch = 0; ch < 4; ++ch) {
            tc_ld_x32(r, tmem + ch * 32);
            tc_wait_ld();
            if (storeT) {
                #pragma unroll
                for (int c = 0; c < 32; ++c)
                    C[(uint32_t)(ch * 32 + c) * N_ROWS + m] = rna_tf32(__uint_as_float(r[c]));
            } else {
                float4* dst = reinterpret_cast<float4*>(&C[(size_t)m * D_OUT + ch * 32]);
                #pragma unroll
                for (int j = 0; j < 8; ++j)
                    dst[j] = make_float4(__uint_as_float(r[4*j]),   __uint_as_float(r[4*j+1]),
                                         __uint_as_float(r[4*j+2]), __uint_as_float(r[4*j+3]));
            }
        }
    }
    tc_fence_before();
    __syncthreads();
    if (wid == 0) tc_dealloc(tmem);
#else
    else if (wid < 8) {               // ---- fallback: mma.sync.tf32 consumers ----
        int wm = wid & 3, wn = wid >> 2;
        float acc[64];
        #pragma unroll
        for (int i = 0; i < 64; ++i) acc[i] = 0.f;

        int s = 0, ph = 0;
        for (int it = 0; it < kIters; ++it) {
            mbar_wait_acq(ab + s*16, ph);
            uint32_t aB = TILE0 + s * STAGE_BYTES;
            uint32_t bB = aB + A_BYTES;
            int r0 = wm * 32 + (lane >> 2);
            #pragma unroll
            for (int ks = 0; ks < 4; ++ks) {
                int c0 = ks * 8 + (lane & 3);
                uint32_t a[8];
                #pragma unroll
                for (int mf = 0; mf < 2; ++mf) {
                    int r = r0 + mf * 16;
                    a[mf*4+0] = lds32(aB + sw128((uint32_t)(r     *128 +  c0     *4)));
                    a[mf*4+1] = lds32(aB + sw128((uint32_t)((r+8) *128 +  c0     *4)));
                    a[mf*4+2] = lds32(aB + sw128((uint32_t)(r     *128 + (c0+4)  *4)));
                    a[mf*4+3] = lds32(aB + sw128((uint32_t)((r+8) *128 + (c0+4)  *4)));
                }
                #pragma unroll
                for (int nf = 0; nf < 8; ++nf) {
                    int n = wn * 64 + nf * 8 + (lane >> 2);
                    uint32_t b0 = lds32(bB + sw128((uint32_t)(n*128 +  c0    *4)));
                    uint32_t b1 = lds32(bB + sw128((uint32_t)(n*128 + (c0+4) *4)));
                    mma_t4(&acc[(0*8 + nf)*4], a,     b0, b1);
                    mma_t4(&acc[(1*8 + nf)*4], a + 4, b0, b1);
                }
            }
            __syncwarp();
            if (lane == 0) mbar_arrive(ab + s*16 + 8);
            if (++s == STAGES) { s = 0; ph ^= 1; }
        }
        #pragma unroll
        for (int mf = 0; mf < 2; ++mf) {
            #pragma unroll
            for (int nf = 0; nf < 8; ++nf) {
                int row = blockIdx.x * MT + wm * 32 + mf * 16 + (lane >> 2);
                int col = wn * 64 + nf * 8 + 2 * (lane & 3);
                float* cc = &acc[(mf*8 + nf)*4];
                if (storeT) {
                    C[(uint32_t)col     * N_ROWS + row    ] = rna_tf32(cc[0]);
                    C[(uint32_t)(col+1) * N_ROWS + row    ] = rna_tf32(cc[1]);
                    C[(uint32_t)col     * N_ROWS + row + 8] = rna_tf32(cc[2]);
                    C[(uint32_t)(col+1) * N_ROWS + row + 8] = rna_tf32(cc[3]);
                } else {
                    *reinterpret_cast<float2*>(&C[(size_t)row     * D_OUT + col]) = make_float2(cc[0], cc[1]);
                    *reinterpret_cast<float2*>(&C[(size_t)(row+8) * D_OUT + col]) = make_float2(cc[2], cc[3]);
                }
            }
        }
    }
    __syncthreads();
#endif
    if (CSZ > 1) cluster_sync_all();   // no exit while peer multicasts may be in flight
}

__global__ void __launch_bounds__(NTHREADS, 1) __cluster_dims__(1, 1, 1)
gemm_c1(const __grid_constant__ CUtensorMap tmA, const __grid_constant__ CUtensorMap tmB,
        float* __restrict__ C, int kIters, int storeT)
{ gemm_body<1>(tmA, tmB, C, kIters, storeT); }

__global__ void __launch_bounds__(NTHREADS, 1) __cluster_dims__(4, 1, 1)
gemm_c4(const __grid_constant__ CUtensorMap tmA, const __grid_constant__ CUtensorMap tmB,
        float* __restrict__ C, int kIters, int storeT)
{ gemm_body<4>(tmA, tmB, C, kIters, storeT); }

// ---------------- prep kernels ----------------
__global__ void kprep_round(const float4* __restrict__ in, float4* __restrict__ out, int n4) {
    int i = blockIdx.x * blockDim.x + threadIdx.x;
    if (i < n4) {
        float4 v = in[i];
        v.x = rna_tf32(v.x); v.y = rna_tf32(v.y);
        v.z = rna_tf32(v.z); v.w = rna_tf32(v.w);
        out[i] = v;
    }
}
__global__ void ktranspose_w(const float* __restrict__ W, float* __restrict__ Wt) {
    __shared__ float tile[32][33];
    int bx = blockIdx.x * 32, by = blockIdx.y * 32;
    int tx = threadIdx.x, ty = threadIdx.y;
    tile[ty][tx] = W[(by + ty) * D_OUT + bx + tx];
    __syncthreads();
    Wt[(bx + ty) * D_IN + by + tx] = rna_tf32(tile[tx][ty]);
}

// ---------------- host ----------------
typedef CUresult (*PFN_tmenc)(CUtensorMap*, CUtensorMapDataType, cuuint32_t, void*,
                              const cuuint64_t*, const cuuint64_t*, const cuuint32_t*,
                              const cuuint32_t*, CUtensorMapInterleave, CUtensorMapSwizzle,
                              CUtensorMapL2promotion, CUtensorMapFloatOOBfill);

static void enc_f32_sw128(PFN_tmenc fn, CUtensorMap* tm, void* p,
                          uint64_t d0, uint64_t d1, uint32_t box1,
                          CUtensorMapL2promotion promo) {
    cuuint64_t dims[2]    = {d0, d1};
    cuuint64_t strides[1] = {d0 * sizeof(float)};
    cuuint32_t box[2]     = {32u, box1};
    cuuint32_t estr[2]    = {1u, 1u};
    fn(tm, CU_TENSOR_MAP_DATA_TYPE_FLOAT32, 2, p, dims, strides, box, estr,
       CU_TENSOR_MAP_INTERLEAVE_NONE, CU_TENSOR_MAP_SWIZZLE_128B,
       promo, CU_TENSOR_MAP_FLOAT_OOB_FILL_NONE);
}

extern "C" void kernel_launch(void* const* d_in, const int* in_sizes, int n_in,
                              void* d_out, int out_size) {
    const float *inputs = nullptr, *adj = nullptr, *W = nullptr;
    for (int i = 0; i < n_in; ++i) {
        if (in_sizes[i] == N_ROWS * D_IN)           inputs = (const float*)d_in[i];
        else if (in_sizes[i] == D_IN * D_OUT)       W      = (const float*)d_in[i];
        else                                        adj    = (const float*)d_in[i];
    }

    void* fp = dlsym(RTLD_DEFAULT, "cuTensorMapEncodeTiled");
    if (!fp) {
        void* h = dlopen("libcuda.so.1", RTLD_NOW | RTLD_GLOBAL);
        if (h) fp = dlsym(h, "cuTensorMapEncodeTiled");
    }
    PFN_tmenc tmenc = (PFN_tmenc)fp;

    void *pWt = nullptr, *pXt = nullptr, *pInR = nullptr;
    cudaGetSymbolAddress(&pWt,  g_Wt);
    cudaGetSymbolAddress(&pXt,  g_Xt);
    cudaGetSymbolAddress(&pInR, g_inR);

    CUtensorMap tmA1, tmB1, tmA2, tmB2;
    enc_f32_sw128(tmenc, &tmA1, pInR, D_IN, N_ROWS, 128, CU_TENSOR_MAP_L2_PROMOTION_L2_128B);
    enc_f32_sw128(tmenc, &tmB1, pWt,  D_IN, D_OUT,  128, CU_TENSOR_MAP_L2_PROMOTION_L2_128B);
    // adj: 256B promotion — the extra 128B sector is next iteration's K-slice (prefetch)
    enc_f32_sw128(tmenc, &tmA2, (void*)adj, N_ROWS, N_ROWS, 128, CU_TENSOR_MAP_L2_PROMOTION_L2_256B);
    // B for GEMM2: 32-row boxes (one cluster slice per load)
    enc_f32_sw128(tmenc, &tmB2, pXt, N_ROWS, D_OUT, 32, CU_TENSOR_MAP_L2_PROMOTION_L2_128B);

    cudaFuncSetAttribute(gemm_c1, cudaFuncAttributeMaxDynamicSharedMemorySize, SMEM_DYN);
    cudaFuncSetAttribute(gemm_c4, cudaFuncAttributeMaxDynamicSharedMemorySize, SMEM_DYN);

    int n4 = N_ROWS * D_IN / 4;
    kprep_round<<<(n4 + 255) / 256, 256>>>((const float4*)inputs, (float4*)pInR, n4);
    ktranspose_w<<<dim3(D_OUT / 32, D_IN / 32), dim3(32, 32)>>>(W, (float*)pWt);

    // GEMM1: Xt = (inputs @ W)^T   K=512 (no multicast needed, B tiny)
    gemm_c1<<<N_ROWS / MT, NTHREADS, SMEM_DYN>>>(tmA1, tmB1, (float*)pXt, D_IN / KT, 1);
    // GEMM2: out = adj @ X         K=16384, cluster-4 B multicast
    gemm_c4<<<N_ROWS / MT, NTHREADS, SMEM_DYN>>>(tmA2, tmB2, (float*)d_out, N_ROWS / KT, 0);
}

// round 8
// speedup vs baseline: 1.0670x; 1.0670x over previous
#include <cuda_runtime.h>
#include <cuda.h>
#include <cstdint>
#include <dlfcn.h>

#if defined(__CUDA_ARCH__) && (defined(__CUDA_ARCH_FEAT_SM103_ALL) || defined(__CUDA_ARCH_SPECIFIC__) || defined(__CUDA_ARCH_FAMILY_SPECIFIC__))
#define HAS_TCG 1
#else
#define HAS_TCG 0
#endif

#define N_ROWS 16384
#define D_IN   512
#define D_OUT  128

#define KT 32                       // K per stage (32 fp32 = 128B rows, SW128)
#define MT 128
#define STAGES 6
#define A_BYTES 16384               // 128 rows x 128B
#define B_BYTES 16384
#define STAGE_BYTES (A_BYTES + B_BYTES)
#define SMEM_DYN (2048 + STAGES * STAGE_BYTES)
#define NTHREADS 320                // warps 0-7 compute (fallback), 8 producer, 9 tcg issuer

// Mean relative shrink of fp32->tf32 truncation: 2^-10 * 0.5 * ln2 ~= 3.39e-4.
// One factor compensates the A-operand (inputs) truncation in GEMM1 (folded into Wt),
// one compensates the adj truncation in GEMM2 (folded into Xt).
#define TRUNC_COMP 1.000339f

// idesc kind::tf32: dtype F32=1<<4, atype TF32=2<<7, btype TF32=2<<10, N/8<<17, M/16<<24
#define IDESC_TF32 ((1u << 4) | (2u << 7) | (2u << 10) | (16u << 17) | (8u << 24))

// Static scratch (allocation-free)
__device__ __align__(1024) float g_Wt[D_OUT * D_IN];
__device__ __align__(1024) float g_Xt[(size_t)D_OUT * N_ROWS];

// ---------------- helpers (non-arch-specific) ----------------
__device__ __forceinline__ uint32_t smem_u32(const void* p) {
    uint32_t a;
    asm("{ .reg .u64 t; cvta.to.shared.u64 t, %1; cvt.u32.u64 %0, t; }" : "=r"(a) : "l"(p));
    return a;
}
__device__ __forceinline__ float rna_tf32(float x) {
    float r; asm("cvt.rna.tf32.f32 %0, %1;" : "=f"(r) : "f"(x));
    return r;
}
__device__ __forceinline__ void mbar_init(uint32_t a, uint32_t cnt) {
    asm volatile("mbarrier.init.shared.b64 [%0], %1;" :: "r"(a), "r"(cnt) : "memory");
}
__device__ __forceinline__ void mbar_arrive(uint32_t a) {
    asm volatile("mbarrier.arrive.shared.b64 _, [%0];" :: "r"(a) : "memory");
}
__device__ __forceinline__ void mbar_expect_tx(uint32_t a, uint32_t bytes) {
    asm volatile("mbarrier.arrive.expect_tx.shared.b64 _, [%0], %1;" :: "r"(a), "r"(bytes) : "memory");
}
__device__ __forceinline__ void mbar_wait_acq(uint32_t a, uint32_t ph) {
    asm volatile("{\n\t.reg .pred P1;\n\t"
                 "WA_%=:\n\t"
                 "mbarrier.try_wait.parity.acquire.cta.shared::cta.b64 P1, [%0], %1, 0x989680;\n\t"
                 "@P1 bra.uni WDA_%=;\n\t"
                 "bra.uni WA_%=;\n\t"
                 "WDA_%=:\n\t}" :: "r"(a), "r"(ph) : "memory");
}
__device__ __forceinline__ void mbar_wait_rel(uint32_t a, uint32_t ph) {
    asm volatile("{\n\t.reg .pred P1;\n\t"
                 "WR_%=:\n\t"
                 "mbarrier.try_wait.parity.relaxed.cta.shared::cta.b64 P1, [%0], %1, 0x989680;\n\t"
                 "@P1 bra.uni WDR_%=;\n\t"
                 "bra.uni WR_%=;\n\t"
                 "WDR_%=:\n\t}" :: "r"(a), "r"(ph) : "memory");
}
__device__ __forceinline__ void tma_load2d(uint32_t dst, const CUtensorMap* tm,
                                           int cx, int cy, uint32_t bar) {
    asm volatile("cp.async.bulk.tensor.2d.shared::cta.global.tile.mbarrier::complete_tx::bytes "
                 "[%0], [%1, {%2, %3}], [%4];"
                 :: "r"(dst), "l"(tm), "r"(cx), "r"(cy), "r"(bar) : "memory");
}
__device__ __forceinline__ uint32_t sw128(uint32_t o) { return o ^ ((o >> 3) & 0x70); }
__device__ __forceinline__ uint32_t lds32(uint32_t a) {
    uint32_t v; asm volatile("ld.shared.b32 %0, [%1];" : "=r"(v) : "r"(a));
    return v;
}
__device__ __forceinline__ void mma_t4(float* c, const uint32_t* a, uint32_t b0, uint32_t b1) {
    asm volatile("mma.sync.aligned.m16n8k8.row.col.f32.tf32.tf32.f32 "
                 "{%0,%1,%2,%3}, {%4,%5,%6,%7}, {%8,%9}, {%0,%1,%2,%3};"
                 : "+f"(c[0]), "+f"(c[1]), "+f"(c[2]), "+f"(c[3])
                 : "r"(a[0]), "r"(a[1]), "r"(a[2]), "r"(a[3]), "r"(b0), "r"(b1));
}

// ---------------- arch-specific helpers ----------------
#if HAS_TCG
__device__ __forceinline__ void tc_alloc(uint32_t saddr) {
    asm volatile("tcgen05.alloc.cta_group::1.sync.aligned.shared::cta.b32 [%0], %1;"
                 :: "r"(saddr), "r"(128) : "memory");
}
__device__ __forceinline__ void tc_relinq() {
    asm volatile("tcgen05.relinquish_alloc_permit.cta_group::1.sync.aligned;");
}
__device__ __forceinline__ void tc_dealloc(uint32_t t) {
    asm volatile("tcgen05.dealloc.cta_group::1.sync.aligned.b32 %0, %1;" :: "r"(t), "r"(128));
}
__device__ __forceinline__ void tc_commit(uint32_t bar) {
    asm volatile("tcgen05.commit.cta_group::1.mbarrier::arrive::one.shared::cluster.b64 [%0];"
                 :: "r"(bar) : "memory");
}
__device__ __forceinline__ void tc_fence_after()  { asm volatile("tcgen05.fence::after_thread_sync;"  ::: "memory"); }
__device__ __forceinline__ void tc_fence_before() { asm volatile("tcgen05.fence::before_thread_sync;" ::: "memory"); }
__device__ __forceinline__ void tc_wait_ld()      { asm volatile("tcgen05.wait::ld.sync.aligned;"     ::: "memory"); }
__device__ __forceinline__ uint64_t sdesc(uint32_t addr) {
    const uint64_t BASE = (2ull << 61) | (1ull << 46) | (64ull << 32) | (1ull << 16);
    return BASE | ((uint64_t)(addr >> 4) & 0x3FFF);
}
__device__ __forceinline__ void mma_tf32(uint32_t d, uint64_t ad, uint64_t bd, uint32_t en) {
    asm volatile("{\n\t.reg .pred p;\n\tsetp.ne.u32 p, %4, 0;\n\t"
                 "tcgen05.mma.cta_group::1.kind::tf32 [%0], %1, %2, %3, {%5, %5, %5, %5}, p;\n\t}"
                 :: "r"(d), "l"(ad), "l"(bd), "r"(IDESC_TF32), "r"(en), "r"(0u) : "memory");
}
__device__ __forceinline__ void tc_ld_x32(uint32_t* r, uint32_t ta) {
    asm volatile("tcgen05.ld.sync.aligned.32x32b.x32.b32 "
        "{%0, %1, %2, %3, %4, %5, %6, %7, "
        " %8, %9, %10, %11, %12, %13, %14, %15, "
        " %16, %17, %18, %19, %20, %21, %22, %23, "
        " %24, %25, %26, %27, %28, %29, %30, %31}, [%32];"
        : "=r"(r[0]),  "=r"(r[1]),  "=r"(r[2]),  "=r"(r[3]),
          "=r"(r[4]),  "=r"(r[5]),  "=r"(r[6]),  "=r"(r[7]),
          "=r"(r[8]),  "=r"(r[9]),  "=r"(r[10]), "=r"(r[11]),
          "=r"(r[12]), "=r"(r[13]), "=r"(r[14]), "=r"(r[15]),
          "=r"(r[16]), "=r"(r[17]), "=r"(r[18]), "=r"(r[19]),
          "=r"(r[20]), "=r"(r[21]), "=r"(r[22]), "=r"(r[23]),
          "=r"(r[24]), "=r"(r[25]), "=r"(r[26]), "=r"(r[27]),
          "=r"(r[28]), "=r"(r[29]), "=r"(r[30]), "=r"(r[31])
        : "r"(ta));
}
#endif

// ---------------- GEMM: C[M,128] = A[M,K] * Bt[128,K]^T ----------------
// storeT: C stored transposed (Xt) with rna-tf32 and TRUNC_COMP scale.
__global__ void __launch_bounds__(NTHREADS, 1) __cluster_dims__(1, 1, 1)
gemm_tf32_n128(const __grid_constant__ CUtensorMap tmA,
               const __grid_constant__ CUtensorMap tmB,
               float* __restrict__ C, int kIters, int storeT)
{
    extern __shared__ __align__(1024) char smem_raw[];
    uint32_t sb = smem_u32(smem_raw);
    uint32_t ab = (sb + 1023u) & ~1023u;
    const uint32_t DONE  = ab + STAGES * 16;
    const uint32_t TPTR  = ab + 128;
    const uint32_t TILE0 = ab + 1024;
    int tid = threadIdx.x, wid = tid >> 5, lane = tid & 31;

#if HAS_TCG
    const uint32_t EMPTY_CNT = 1;     // released by tc_commit
#else
    const uint32_t EMPTY_CNT = 8;     // 8 local consumer warps
#endif
    if (tid == 0) {
        for (int s = 0; s < STAGES; s++) {
            mbar_init(ab + s*16, 1);               // full (tx-based)
            mbar_init(ab + s*16 + 8, EMPTY_CNT);   // empty
        }
        mbar_init(DONE, 1);
    }
#if HAS_TCG
    if (wid == 0) { tc_alloc(TPTR); tc_relinq(); }
#endif
    __syncthreads();

#if HAS_TCG
    uint32_t tmem;
    asm volatile("ld.shared.b32 %0, [%1];" : "=r"(tmem) : "r"(TPTR));
#endif

    if (tid == 256) {                 // ---- producer (warp 8 lane 0) ----
        int s = 0, ph = 1;
        int mo = blockIdx.x * MT;
        for (int it = 0; it < kIters; ++it) {
            mbar_wait_rel(ab + s*16 + 8, ph);
            mbar_expect_tx(ab + s*16, STAGE_BYTES);
            uint32_t base = TILE0 + s * STAGE_BYTES;
            tma_load2d(base,           &tmA, it * KT, mo, ab + s*16);
            tma_load2d(base + A_BYTES, &tmB, it * KT, 0,  ab + s*16);
            if (++s == STAGES) { s = 0; ph ^= 1; }
        }
    }
#if HAS_TCG
    else if (tid == 288) {            // ---- tcgen05 MMA issuer (warp 9 lane 0) ----
        int s = 0, ph = 0;
        for (int it = 0; it < kIters; ++it) {
            mbar_wait_rel(ab + s*16, ph);
            uint32_t base = TILE0 + s * STAGE_BYTES;
            uint64_t ad = sdesc(base), bd = sdesc(base + A_BYTES);
            mma_tf32(tmem, ad,     bd,     it != 0);
            mma_tf32(tmem, ad + 2, bd + 2, 1);
            mma_tf32(tmem, ad + 4, bd + 4, 1);
            mma_tf32(tmem, ad + 6, bd + 6, 1);
            tc_commit(ab + s*16 + 8);
            if (++s == STAGES) { s = 0; ph ^= 1; }
        }
        tc_commit(DONE);
    }
    // ---- epilogue: everyone waits, warps 0-3 drain TMEM ----
    mbar_wait_acq(DONE, 0);
    tc_fence_after();
    if (wid < 4) {
        uint32_t r[32];
        int m = blockIdx.x * MT + wid * 32 + lane;
        #pragma unroll
        for (int ch = 0; ch < 4; ++ch) {
            tc_ld_x32(r, tmem + ch * 32);
            tc_wait_ld();
            if (storeT) {
                #pragma unroll
                for (int c = 0; c < 32; ++c)   // coalesced along m; comp for adj truncation
                    C[(uint32_t)(ch * 32 + c) * N_ROWS + m] =
                        rna_tf32(__uint_as_float(r[c]) * TRUNC_COMP);
            } else {
                float4* dst = reinterpret_cast<float4*>(&C[(size_t)m * D_OUT + ch * 32]);
                #pragma unroll
                for (int j = 0; j < 8; ++j)
                    dst[j] = make_float4(__uint_as_float(r[4*j]),   __uint_as_float(r[4*j+1]),
                                         __uint_as_float(r[4*j+2]), __uint_as_float(r[4*j+3]));
            }
        }
    }
    tc_fence_before();
    __syncthreads();
    if (wid == 0) tc_dealloc(tmem);
#else
    else if (wid < 8) {               // ---- fallback: mma.sync.tf32 consumers ----
        int wm = wid & 3, wn = wid >> 2;
        float acc[64];
        #pragma unroll
        for (int i = 0; i < 64; ++i) acc[i] = 0.f;

        int s = 0, ph = 0;
        for (int it = 0; it < kIters; ++it) {
            mbar_wait_acq(ab + s*16, ph);
            uint32_t aB = TILE0 + s * STAGE_BYTES;
            uint32_t bB = aB + A_BYTES;
            int r0 = wm * 32 + (lane >> 2);
            #pragma unroll
            for (int ks = 0; ks < 4; ++ks) {
                int c0 = ks * 8 + (lane & 3);
                uint32_t a[8];
                #pragma unroll
                for (int mf = 0; mf < 2; ++mf) {
                    int r = r0 + mf * 16;
                    a[mf*4+0] = lds32(aB + sw128((uint32_t)(r     *128 +  c0     *4)));
                    a[mf*4+1] = lds32(aB + sw128((uint32_t)((r+8) *128 +  c0     *4)));
                    a[mf*4+2] = lds32(aB + sw128((uint32_t)(r     *128 + (c0+4)  *4)));
                    a[mf*4+3] = lds32(aB + sw128((uint32_t)((r+8) *128 + (c0+4)  *4)));
                }
                #pragma unroll
                for (int nf = 0; nf < 8; ++nf) {
                    int n = wn * 64 + nf * 8 + (lane >> 2);
                    uint32_t b0 = lds32(bB + sw128((uint32_t)(n*128 +  c0    *4)));
                    uint32_t b1 = lds32(bB + sw128((uint32_t)(n*128 + (c0+4) *4)));
                    mma_t4(&acc[(0*8 + nf)*4], a,     b0, b1);
                    mma_t4(&acc[(1*8 + nf)*4], a + 4, b0, b1);
                }
            }
            __syncwarp();
            if (lane == 0) mbar_arrive(ab + s*16 + 8);
            if (++s == STAGES) { s = 0; ph ^= 1; }
        }
        #pragma unroll
        for (int mf = 0; mf < 2; ++mf) {
            #pragma unroll
            for (int nf = 0; nf < 8; ++nf) {
                int row = blockIdx.x * MT + wm * 32 + mf * 16 + (lane >> 2);
                int col = wn * 64 + nf * 8 + 2 * (lane & 3);
                float* cc = &acc[(mf*8 + nf)*4];
                if (storeT) {
                    C[(uint32_t)col     * N_ROWS + row    ] = rna_tf32(cc[0] * TRUNC_COMP);
                    C[(uint32_t)(col+1) * N_ROWS + row    ] = rna_tf32(cc[1] * TRUNC_COMP);
                    C[(uint32_t)col     * N_ROWS + row + 8] = rna_tf32(cc[2] * TRUNC_COMP);
                    C[(uint32_t)(col+1) * N_ROWS + row + 8] = rna_tf32(cc[3] * TRUNC_COMP);
                } else {
                    *reinterpret_cast<float2*>(&C[(size_t)row     * D_OUT + col]) = make_float2(cc[0], cc[1]);
                    *reinterpret_cast<float2*>(&C[(size_t)(row+8) * D_OUT + col]) = make_float2(cc[2], cc[3]);
                }
            }
        }
    }
    __syncthreads();
#endif
}

// ---------------- prep: W transpose with truncation compensation ----------------
// Wt = rna(W^T * TRUNC_COMP) — the scale compensates the mean shrink from the
// hardware tf32 truncation of the (un-prerounded) A operand (inputs) in GEMM1.
__global__ void ktranspose_w(const float* __restrict__ W, float* __restrict__ Wt) {
    __shared__ float tile[32][33];
    int bx = blockIdx.x * 32, by = blockIdx.y * 32;       // bx: n-dim, by: k-dim
    int tx = threadIdx.x, ty = threadIdx.y;
    tile[ty][tx] = W[(by + ty) * D_OUT + bx + tx];
    __syncthreads();
    Wt[(bx + ty) * D_IN + by + tx] = rna_tf32(tile[tx][ty] * TRUNC_COMP);
}

// ---------------- host ----------------
typedef CUresult (*PFN_tmenc)(CUtensorMap*, CUtensorMapDataType, cuuint32_t, void*,
                              const cuuint64_t*, const cuuint64_t*, const cuuint32_t*,
                              const cuuint32_t*, CUtensorMapInterleave, CUtensorMapSwizzle,
                              CUtensorMapL2promotion, CUtensorMapFloatOOBfill);

static void enc_f32_sw128(PFN_tmenc fn, CUtensorMap* tm, void* p,
                          uint64_t d0, uint64_t d1) {
    cuuint64_t dims[2]    = {d0, d1};
    cuuint64_t strides[1] = {d0 * sizeof(float)};
    cuuint32_t box[2]     = {32u, 128u};
    cuuint32_t estr[2]    = {1u, 1u};
    fn(tm, CU_TENSOR_MAP_DATA_TYPE_FLOAT32, 2, p, dims, strides, box, estr,
       CU_TENSOR_MAP_INTERLEAVE_NONE, CU_TENSOR_MAP_SWIZZLE_128B,
       CU_TENSOR_MAP_L2_PROMOTION_L2_128B, CU_TENSOR_MAP_FLOAT_OOB_FILL_NONE);
}

extern "C" void kernel_launch(void* const* d_in, const int* in_sizes, int n_in,
                              void* d_out, int out_size) {
    const float *inputs = nullptr, *adj = nullptr, *W = nullptr;
    for (int i = 0; i < n_in; ++i) {
        if (in_sizes[i] == N_ROWS * D_IN)           inputs = (const float*)d_in[i];
        else if (in_sizes[i] == D_IN * D_OUT)       W      = (const float*)d_in[i];
        else                                        adj    = (const float*)d_in[i];
    }

    void* fp = dlsym(RTLD_DEFAULT, "cuTensorMapEncodeTiled");
    if (!fp) {
        void* h = dlopen("libcuda.so.1", RTLD_NOW | RTLD_GLOBAL);
        if (h) fp = dlsym(h, "cuTensorMapEncodeTiled");
    }
    PFN_tmenc tmenc = (PFN_tmenc)fp;

    void *pWt = nullptr, *pXt = nullptr;
    cudaGetSymbolAddress(&pWt,  g_Wt);
    cudaGetSymbolAddress(&pXt,  g_Xt);

    CUtensorMap tmA1, tmB1, tmA2, tmB2;
    enc_f32_sw128(tmenc, &tmA1, (void*)inputs, D_IN,   N_ROWS);  // raw inputs (HW-truncated, bias folded into Wt)
    enc_f32_sw128(tmenc, &tmB1, pWt,           D_IN,   D_OUT);   // W^T * comp
    enc_f32_sw128(tmenc, &tmA2, (void*)adj,    N_ROWS, N_ROWS);  // adj
    enc_f32_sw128(tmenc, &tmB2, pXt,           N_ROWS, D_OUT);   // X^T * comp

    cudaFuncSetAttribute(gemm_tf32_n128,
                         cudaFuncAttributeMaxDynamicSharedMemorySize, SMEM_DYN);

    ktranspose_w<<<dim3(D_OUT / 32, D_IN / 32), dim3(32, 32)>>>(W, (float*)pWt);

    // GEMM1: Xt = (inputs @ W)^T   K=512
    gemm_tf32_n128<<<N_ROWS / MT, NTHREADS, SMEM_DYN>>>(tmA1, tmB1, (float*)pXt, D_IN / KT, 1);
    // GEMM2: out = adj @ X         K=16384
    gemm_tf32_n128<<<N_ROWS / MT, NTHREADS, SMEM_DYN>>>(tmA2, tmB2, (float*)d_out, N_ROWS / KT, 0);
}

// round 11
// speedup vs baseline: 1.1234x; 1.0529x over previous
#include <cuda_runtime.h>
#include <cuda.h>
#include <cstdint>
#include <dlfcn.h>

#if defined(__CUDA_ARCH__) && (defined(__CUDA_ARCH_FEAT_SM103_ALL) || defined(__CUDA_ARCH_SPECIFIC__) || defined(__CUDA_ARCH_FAMILY_SPECIFIC__))
#define HAS_TCG 1
#else
#define HAS_TCG 0
#endif

#define N_ROWS 16384
#define D_IN   512
#define D_OUT  128

#define KT 32                       // K per stage (32 fp32 = 128B rows, SW128)
#define MT 128
#define STAGES 6
#define A_BYTES 16384               // 128 rows x 128B
#define B_BYTES 16384
#define STAGE_BYTES (A_BYTES + B_BYTES)
#define SMEM_DYN (2048 + STAGES * STAGE_BYTES)
#define NTHREADS 320                // warps 0-7 compute (fallback), 8 producer, 9 tcg issuer

// Mean relative shrink of fp32->tf32 truncation: 2^-10 * 0.5 * ln2 ~= 3.39e-4.
// One factor compensates the A-operand (inputs) truncation in GEMM1 (folded into Wt),
// one compensates the adj truncation in GEMM2 (folded into Xt).
#define TRUNC_COMP 1.000339f

// idesc kind::tf32: dtype F32=1<<4, atype TF32=2<<7, btype TF32=2<<10, N/8<<17, M/16<<24
#define IDESC_TF32 ((1u << 4) | (2u << 7) | (2u << 10) | (16u << 17) | (8u << 24))

// Static scratch (allocation-free)
__device__ __align__(1024) float g_Wt[D_OUT * D_IN];
__device__ __align__(1024) float g_Xt[(size_t)D_OUT * N_ROWS];

// ---------------- helpers (non-arch-specific) ----------------
__device__ __forceinline__ uint32_t smem_u32(const void* p) {
    uint32_t a;
    asm("{ .reg .u64 t; cvta.to.shared.u64 t, %1; cvt.u32.u64 %0, t; }" : "=r"(a) : "l"(p));
    return a;
}
__device__ __forceinline__ float rna_tf32(float x) {
    float r; asm("cvt.rna.tf32.f32 %0, %1;" : "=f"(r) : "f"(x));
    return r;
}
__device__ __forceinline__ void mbar_init(uint32_t a, uint32_t cnt) {
    asm volatile("mbarrier.init.shared.b64 [%0], %1;" :: "r"(a), "r"(cnt) : "memory");
}
__device__ __forceinline__ void mbar_arrive(uint32_t a) {
    asm volatile("mbarrier.arrive.shared.b64 _, [%0];" :: "r"(a) : "memory");
}
__device__ __forceinline__ void mbar_expect_tx(uint32_t a, uint32_t bytes) {
    asm volatile("mbarrier.arrive.expect_tx.shared.b64 _, [%0], %1;" :: "r"(a), "r"(bytes) : "memory");
}
__device__ __forceinline__ void mbar_wait_acq(uint32_t a, uint32_t ph) {
    asm volatile("{\n\t.reg .pred P1;\n\t"
                 "WA_%=:\n\t"
                 "mbarrier.try_wait.parity.acquire.cta.shared::cta.b64 P1, [%0], %1, 0x989680;\n\t"
                 "@P1 bra.uni WDA_%=;\n\t"
                 "bra.uni WA_%=;\n\t"
                 "WDA_%=:\n\t}" :: "r"(a), "r"(ph) : "memory");
}
__device__ __forceinline__ void mbar_wait_rel(uint32_t a, uint32_t ph) {
    asm volatile("{\n\t.reg .pred P1;\n\t"
                 "WR_%=:\n\t"
                 "mbarrier.try_wait.parity.relaxed.cta.shared::cta.b64 P1, [%0], %1, 0x989680;\n\t"
                 "@P1 bra.uni WDR_%=;\n\t"
                 "bra.uni WR_%=;\n\t"
                 "WDR_%=:\n\t}" :: "r"(a), "r"(ph) : "memory");
}
__device__ __forceinline__ void tma_load2d(uint32_t dst, const CUtensorMap* tm,
                                           int cx, int cy, uint32_t bar) {
    asm volatile("cp.async.bulk.tensor.2d.shared::cta.global.tile.mbarrier::complete_tx::bytes "
                 "[%0], [%1, {%2, %3}], [%4];"
                 :: "r"(dst), "l"(tm), "r"(cx), "r"(cy), "r"(bar) : "memory");
}
__device__ __forceinline__ uint32_t sw128(uint32_t o) { return o ^ ((o >> 3) & 0x70); }
__device__ __forceinline__ uint32_t lds32(uint32_t a) {
    uint32_t v; asm volatile("ld.shared.b32 %0, [%1];" : "=r"(v) : "r"(a));
    return v;
}
__device__ __forceinline__ void mma_t4(float* c, const uint32_t* a, uint32_t b0, uint32_t b1) {
    asm volatile("mma.sync.aligned.m16n8k8.row.col.f32.tf32.tf32.f32 "
                 "{%0,%1,%2,%3}, {%4,%5,%6,%7}, {%8,%9}, {%0,%1,%2,%3};"
                 : "+f"(c[0]), "+f"(c[1]), "+f"(c[2]), "+f"(c[3])
                 : "r"(a[0]), "r"(a[1]), "r"(a[2]), "r"(a[3]), "r"(b0), "r"(b1));
}

// ---------------- arch-specific helpers ----------------
#if HAS_TCG
__device__ __forceinline__ void tc_alloc(uint32_t saddr) {
    asm volatile("tcgen05.alloc.cta_group::1.sync.aligned.shared::cta.b32 [%0], %1;"
                 :: "r"(saddr), "r"(128) : "memory");
}
__device__ __forceinline__ void tc_relinq() {
    asm volatile("tcgen05.relinquish_alloc_permit.cta_group::1.sync.aligned;");
}
__device__ __forceinline__ void tc_dealloc(uint32_t t) {
    asm volatile("tcgen05.dealloc.cta_group::1.sync.aligned.b32 %0, %1;" :: "r"(t), "r"(128));
}
__device__ __forceinline__ void tc_commit(uint32_t bar) {
    asm volatile("tcgen05.commit.cta_group::1.mbarrier::arrive::one.shared::cluster.b64 [%0];"
                 :: "r"(bar) : "memory");
}
__device__ __forceinline__ void tc_fence_after()  { asm volatile("tcgen05.fence::after_thread_sync;"  ::: "memory"); }
__device__ __forceinline__ void tc_fence_before() { asm volatile("tcgen05.fence::before_thread_sync;" ::: "memory"); }
__device__ __forceinline__ void tc_wait_ld()      { asm volatile("tcgen05.wait::ld.sync.aligned;"     ::: "memory"); }
__device__ __forceinline__ uint64_t sdesc(uint32_t addr) {
    const uint64_t BASE = (2ull << 61) | (1ull << 46) | (64ull << 32) | (1ull << 16);
    return BASE | ((uint64_t)(addr >> 4) & 0x3FFF);
}
__device__ __forceinline__ void mma_tf32(uint32_t d, uint64_t ad, uint64_t bd, uint32_t en) {
    asm volatile("{\n\t.reg .pred p;\n\tsetp.ne.u32 p, %4, 0;\n\t"
                 "tcgen05.mma.cta_group::1.kind::tf32 [%0], %1, %2, %3, {%5, %5, %5, %5}, p;\n\t}"
                 :: "r"(d), "l"(ad), "l"(bd), "r"(IDESC_TF32), "r"(en), "r"(0u) : "memory");
}
__device__ __forceinline__ void tc_ld_x32(uint32_t* r, uint32_t ta) {
    asm volatile("tcgen05.ld.sync.aligned.32x32b.x32.b32 "
        "{%0, %1, %2, %3, %4, %5, %6, %7, "
        " %8, %9, %10, %11, %12, %13, %14, %15, "
        " %16, %17, %18, %19, %20, %21, %22, %23, "
        " %24, %25, %26, %27, %28, %29, %30, %31}, [%32];"
        : "=r"(r[0]),  "=r"(r[1]),  "=r"(r[2]),  "=r"(r[3]),
          "=r"(r[4]),  "=r"(r[5]),  "=r"(r[6]),  "=r"(r[7]),
          "=r"(r[8]),  "=r"(r[9]),  "=r"(r[10]), "=r"(r[11]),
          "=r"(r[12]), "=r"(r[13]), "=r"(r[14]), "=r"(r[15]),
          "=r"(r[16]), "=r"(r[17]), "=r"(r[18]), "=r"(r[19]),
          "=r"(r[20]), "=r"(r[21]), "=r"(r[22]), "=r"(r[23]),
          "=r"(r[24]), "=r"(r[25]), "=r"(r[26]), "=r"(r[27]),
          "=r"(r[28]), "=r"(r[29]), "=r"(r[30]), "=r"(r[31])
        : "r"(ta));
}
#endif

// ---------------- GEMM: C[M,128] = A[M,K] * Bt[128,K]^T ----------------
// storeT: C stored transposed (Xt) with rna-tf32 and TRUNC_COMP scale.
__global__ void __launch_bounds__(NTHREADS, 1) __cluster_dims__(1, 1, 1)
gemm_tf32_n128(const __grid_constant__ CUtensorMap tmA,
               const __grid_constant__ CUtensorMap tmB,
               float* __restrict__ C, int kIters, int storeT)
{
    extern __shared__ __align__(1024) char smem_raw[];
    uint32_t sb = smem_u32(smem_raw);
    uint32_t ab = (sb + 1023u) & ~1023u;
    const uint32_t DONE  = ab + STAGES * 16;
    const uint32_t TPTR  = ab + 128;
    const uint32_t TILE0 = ab + 1024;
    int tid = threadIdx.x, wid = tid >> 5, lane = tid & 31;

#if HAS_TCG
    const uint32_t EMPTY_CNT = 1;     // released by tc_commit
#else
    const uint32_t EMPTY_CNT = 8;     // 8 local consumer warps
#endif
    if (tid == 0) {
        for (int s = 0; s < STAGES; s++) {
            mbar_init(ab + s*16, 1);               // full (tx-based)
            mbar_init(ab + s*16 + 8, EMPTY_CNT);   // empty
        }
        mbar_init(DONE, 1);
    }
#if HAS_TCG
    if (wid == 0) { tc_alloc(TPTR); tc_relinq(); }
#endif
    __syncthreads();

#if HAS_TCG
    uint32_t tmem;
    asm volatile("ld.shared.b32 %0, [%1];" : "=r"(tmem) : "r"(TPTR));
#endif

    if (tid == 256) {                 // ---- producer (warp 8 lane 0) ----
        int s = 0, ph = 1;
        int mo = blockIdx.x * MT;
        for (int it = 0; it < kIters; ++it) {
            mbar_wait_rel(ab + s*16 + 8, ph);
            mbar_expect_tx(ab + s*16, STAGE_BYTES);
            uint32_t base = TILE0 + s * STAGE_BYTES;
            tma_load2d(base,           &tmA, it * KT, mo, ab + s*16);
            tma_load2d(base + A_BYTES, &tmB, it * KT, 0,  ab + s*16);
            if (++s == STAGES) { s = 0; ph ^= 1; }
        }
    }
#if HAS_TCG
    else if (tid == 288) {            // ---- tcgen05 MMA issuer (warp 9 lane 0) ----
        int s = 0, ph = 0;
        for (int it = 0; it < kIters; ++it) {
            mbar_wait_rel(ab + s*16, ph);
            uint32_t base = TILE0 + s * STAGE_BYTES;
            uint64_t ad = sdesc(base), bd = sdesc(base + A_BYTES);
            mma_tf32(tmem, ad,     bd,     it != 0);
            mma_tf32(tmem, ad + 2, bd + 2, 1);
            mma_tf32(tmem, ad + 4, bd + 4, 1);
            mma_tf32(tmem, ad + 6, bd + 6, 1);
            tc_commit(ab + s*16 + 8);
            if (++s == STAGES) { s = 0; ph ^= 1; }
        }
        tc_commit(DONE);
    }
    // ---- epilogue: everyone waits, warps 0-3 drain TMEM ----
    mbar_wait_acq(DONE, 0);
    tc_fence_after();
    if (wid < 4) {
        uint32_t r[32];
        int m = blockIdx.x * MT + wid * 32 + lane;
        #pragma unroll
        for (int ch = 0; ch < 4; ++ch) {
            tc_ld_x32(r, tmem + ch * 32);
            tc_wait_ld();
            if (storeT) {
                #pragma unroll
                for (int c = 0; c < 32; ++c)   // coalesced along m; comp for adj truncation
                    C[(uint32_t)(ch * 32 + c) * N_ROWS + m] =
                        rna_tf32(__uint_as_float(r[c]) * TRUNC_COMP);
            } else {
                float4* dst = reinterpret_cast<float4*>(&C[(size_t)m * D_OUT + ch * 32]);
                #pragma unroll
                for (int j = 0; j < 8; ++j)
                    dst[j] = make_float4(__uint_as_float(r[4*j]),   __uint_as_float(r[4*j+1]),
                                         __uint_as_float(r[4*j+2]), __uint_as_float(r[4*j+3]));
            }
        }
    }
    tc_fence_before();
    __syncthreads();
    if (wid == 0) tc_dealloc(tmem);
#else
    else if (wid < 8) {               // ---- fallback: mma.sync.tf32 consumers ----
        int wm = wid & 3, wn = wid >> 2;
        float acc[64];
        #pragma unroll
        for (int i = 0; i < 64; ++i) acc[i] = 0.f;

        int s = 0, ph = 0;
        for (int it = 0; it < kIters; ++it) {
            mbar_wait_acq(ab + s*16, ph);
            uint32_t aB = TILE0 + s * STAGE_BYTES;
            uint32_t bB = aB + A_BYTES;
            int r0 = wm * 32 + (lane >> 2);
            #pragma unroll
            for (int ks = 0; ks < 4; ++ks) {
                int c0 = ks * 8 + (lane & 3);
                uint32_t a[8];
                #pragma unroll
                for (int mf = 0; mf < 2; ++mf) {
                    int r = r0 + mf * 16;
                    a[mf*4+0] = lds32(aB + sw128((uint32_t)(r     *128 +  c0     *4)));
                    a[mf*4+1] = lds32(aB + sw128((uint32_t)((r+8) *128 +  c0     *4)));
                    a[mf*4+2] = lds32(aB + sw128((uint32_t)(r     *128 + (c0+4)  *4)));
                    a[mf*4+3] = lds32(aB + sw128((uint32_t)((r+8) *128 + (c0+4)  *4)));
                }
                #pragma unroll
                for (int nf = 0; nf < 8; ++nf) {
                    int n = wn * 64 + nf * 8 + (lane >> 2);
                    uint32_t b0 = lds32(bB + sw128((uint32_t)(n*128 +  c0    *4)));
                    uint32_t b1 = lds32(bB + sw128((uint32_t)(n*128 + (c0+4) *4)));
                    mma_t4(&acc[(0*8 + nf)*4], a,     b0, b1);
                    mma_t4(&acc[(1*8 + nf)*4], a + 4, b0, b1);
                }
            }
            __syncwarp();
            if (lane == 0) mbar_arrive(ab + s*16 + 8);
            if (++s == STAGES) { s = 0; ph ^= 1; }
        }
        #pragma unroll
        for (int mf = 0; mf < 2; ++mf) {
            #pragma unroll
            for (int nf = 0; nf < 8; ++nf) {
                int row = blockIdx.x * MT + wm * 32 + mf * 16 + (lane >> 2);
                int col = wn * 64 + nf * 8 + 2 * (lane & 3);
                float* cc = &acc[(mf*8 + nf)*4];
                if (storeT) {
                    C[(uint32_t)col     * N_ROWS + row    ] = rna_tf32(cc[0] * TRUNC_COMP);
                    C[(uint32_t)(col+1) * N_ROWS + row    ] = rna_tf32(cc[1] * TRUNC_COMP);
                    C[(uint32_t)col     * N_ROWS + row + 8] = rna_tf32(cc[2] * TRUNC_COMP);
                    C[(uint32_t)(col+1) * N_ROWS + row + 8] = rna_tf32(cc[3] * TRUNC_COMP);
                } else {
                    *reinterpret_cast<float2*>(&C[(size_t)row     * D_OUT + col]) = make_float2(cc[0], cc[1]);
                    *reinterpret_cast<float2*>(&C[(size_t)(row+8) * D_OUT + col]) = make_float2(cc[2], cc[3]);
                }
            }
        }
    }
    __syncthreads();
#endif
}

// ---------------- prep: W transpose with truncation compensation ----------------
// Wt = rna(W^T * TRUNC_COMP). 256 threads/block, 4 elements/thread for ILP
// (the old 1-elem/thread version was a single LDG->STS->bar->LDS->STG chain,
// 4.3us for 512KB). Block (32,8), 32x32 tile, 4 rows per thread each side.
__global__ void ktranspose_w(const float* __restrict__ W, float* __restrict__ Wt) {
    __shared__ float tile[32][33];
    int bx = blockIdx.x * 32, by = blockIdx.y * 32;       // bx: n-dim, by: k-dim
    int tx = threadIdx.x, ty = threadIdx.y;               // (32, 8)
    #pragma unroll
    for (int j = 0; j < 4; ++j)
        tile[ty * 4 + j][tx] = W[(by + ty * 4 + j) * D_OUT + bx + tx];
    __syncthreads();
    #pragma unroll
    for (int j = 0; j < 4; ++j)
        Wt[(bx + ty * 4 + j) * D_IN + by + tx] = rna_tf32(tile[tx][ty * 4 + j] * TRUNC_COMP);
}

// ---------------- host ----------------
typedef CUresult (*PFN_tmenc)(CUtensorMap*, CUtensorMapDataType, cuuint32_t, void*,
                              const cuuint64_t*, const cuuint64_t*, const cuuint32_t*,
                              const cuuint32_t*, CUtensorMapInterleave, CUtensorMapSwizzle,
                              CUtensorMapL2promotion, CUtensorMapFloatOOBfill);

static void enc_f32_sw128(PFN_tmenc fn, CUtensorMap* tm, void* p,
                          uint64_t d0, uint64_t d1, CUtensorMapL2promotion promo) {
    cuuint64_t dims[2]    = {d0, d1};
    cuuint64_t strides[1] = {d0 * sizeof(float)};
    cuuint32_t box[2]     = {32u, 128u};
    cuuint32_t estr[2]    = {1u, 1u};
    fn(tm, CU_TENSOR_MAP_DATA_TYPE_FLOAT32, 2, p, dims, strides, box, estr,
       CU_TENSOR_MAP_INTERLEAVE_NONE, CU_TENSOR_MAP_SWIZZLE_128B,
       promo, CU_TENSOR_MAP_FLOAT_OOB_FILL_NONE);
}

extern "C" void kernel_launch(void* const* d_in, const int* in_sizes, int n_in,
                              void* d_out, int out_size) {
    const float *inputs = nullptr, *adj = nullptr, *W = nullptr;
    for (int i = 0; i < n_in; ++i) {
        if (in_sizes[i] == N_ROWS * D_IN)           inputs = (const float*)d_in[i];
        else if (in_sizes[i] == D_IN * D_OUT)       W      = (const float*)d_in[i];
        else                                        adj    = (const float*)d_in[i];
    }

    void* fp = dlsym(RTLD_DEFAULT, "cuTensorMapEncodeTiled");
    if (!fp) {
        void* h = dlopen("libcuda.so.1", RTLD_NOW | RTLD_GLOBAL);
        if (h) fp = dlsym(h, "cuTensorMapEncodeTiled");
    }
    PFN_tmenc tmenc = (PFN_tmenc)fp;

    void *pWt = nullptr, *pXt = nullptr;
    cudaGetSymbolAddress(&pWt,  g_Wt);
    cudaGetSymbolAddress(&pXt,  g_Xt);

    CUtensorMap tmA1, tmB1, tmA2, tmB2;
    enc_f32_sw128(tmenc, &tmA1, (void*)inputs, D_IN,   N_ROWS, CU_TENSOR_MAP_L2_PROMOTION_L2_128B);
    enc_f32_sw128(tmenc, &tmB1, pWt,           D_IN,   D_OUT,  CU_TENSOR_MAP_L2_PROMOTION_L2_128B);
    // adj: 256B promotion — the adjacent 128B sector is exactly next K-iter's
    // slice of the same rows; halves DRAM request count (isolated test vs R5).
    enc_f32_sw128(tmenc, &tmA2, (void*)adj,    N_ROWS, N_ROWS, CU_TENSOR_MAP_L2_PROMOTION_L2_256B);
    enc_f32_sw128(tmenc, &tmB2, pXt,           N_ROWS, D_OUT,  CU_TENSOR_MAP_L2_PROMOTION_L2_128B);

    cudaFuncSetAttribute(gemm_tf32_n128,
                         cudaFuncAttributeMaxDynamicSharedMemorySize, SMEM_DYN);

    ktranspose_w<<<dim3(D_OUT / 32, D_IN / 32), dim3(32, 8)>>>(W, (float*)pWt);

    // GEMM1: Xt = (inputs @ W)^T   K=512
    gemm_tf32_n128<<<N_ROWS / MT, NTHREADS, SMEM_DYN>>>(tmA1, tmB1, (float*)pXt, D_IN / KT, 1);
    // GEMM2: out = adj @ X         K=16384
    gemm_tf32_n128<<<N_ROWS / MT, NTHREADS, SMEM_DYN>>>(tmA2, tmB2, (float*)d_out, N_ROWS / KT, 0);
}